// round 7
// baseline (speedup 1.0000x reference)
#include <cuda_runtime.h>
#include <cstdint>

#define NB 8
#define NC 19
#define NH 512
#define NW 512
#define HW (NH * NW)            // 262144
#define NPIX (NB * HW)          // 2097152
#define NPAIR (HW / 2)          // 131072 pixel pairs

// g_acc: [0..18] probs_sum_c, [19..37] inter_c, [38] focal [39] nll [40] slp [41] bnll
#define NACC 42

__device__ float g_acc[NACC];
__device__ int g_cnt[NC];
__device__ unsigned int g_ticket;
__device__ unsigned char g_diff[HW];

// ---------------------------------------------------------------------------
// Row-diff + target histogram with per-thread private smem bins.
#define DB 128
#define DG ((HW / 4) / DB)      // 512 blocks

__global__ __launch_bounds__(DB) void diff_kernel(const int* __restrict__ tgt) {
    __shared__ unsigned int s_h[DB][NC];
#pragma unroll
    for (int c = 0; c < NC; c++) s_h[threadIdx.x][c] = 0u;

    const int idx = blockIdx.x * DB + threadIdx.x;      // over HW/4
    const int h = idx >> 7;
    const bool interior = (h >= 1) && (h <= NH - 2);
    const int4* t4 = (const int4*)tgt;

    uchar4 d = make_uchar4(0, 0, 0, 0);
#pragma unroll
    for (int b = 0; b < NB; b++) {
        int base = b * (HW / 4) + idx;
        int4 m = __ldg(t4 + base);
        s_h[threadIdx.x][m.x]++;
        s_h[threadIdx.x][m.y]++;
        s_h[threadIdx.x][m.z]++;
        s_h[threadIdx.x][m.w]++;
        if (interior) {
            int4 a = __ldg(t4 + base - NW / 4);
            int4 q = __ldg(t4 + base + NW / 4);
            d.x |= (unsigned char)((a.x != m.x) | (a.x != q.x));
            d.y |= (unsigned char)((a.y != m.y) | (a.y != q.y));
            d.z |= (unsigned char)((a.z != m.z) | (a.z != q.z));
            d.w |= (unsigned char)((a.w != m.w) | (a.w != q.w));
        }
    }
    ((uchar4*)g_diff)[idx] = d;

    __syncthreads();
    if (threadIdx.x < NC) {
        unsigned int s = 0;
#pragma unroll 8
        for (int r = 0; r < DB; r++) s += s_h[r][threadIdx.x];
        atomicAdd(&g_cnt[threadIdx.x], (int)s);
    }
}

// ---------------------------------------------------------------------------
__device__ __forceinline__ float warp_sum(float v) {
#pragma unroll
    for (int o = 16; o; o >>= 1) v += __shfl_down_sync(0xffffffffu, v, o);
    return v;
}

// ---------------------------------------------------------------------------
// Full-class float2 pairs + L1-hit gather for the target logit (no SEL chain).
#define MAIN_BLOCKS (NPAIR / 256)   // 512

__global__ __launch_bounds__(256) void main_kernel(const float* __restrict__ in,
                                                   const int* __restrict__ tgt,
                                                   float* __restrict__ out) {
    __shared__ float s_int[8][NC];
    __shared__ float s_blk[NACC];
    __shared__ bool s_last;
    {
        int t = threadIdx.x;
        if (t < NACC) s_blk[t] = 0.0f;
        if (t < 8 * NC) ((float*)s_int)[t] = 0.0f;
    }
    __syncthreads();

    const int tidg = blockIdx.x * 256 + threadIdx.x;    // pair index
    const int wid = threadIdx.x >> 5;
    const int lane = threadIdx.x & 31;
    const int hw0 = 2 * tidg;
    const int h = hw0 >> 9;
    const int w0 = hw0 & (NW - 1);

    float bm0 = 0.0f, bm1 = 0.0f;
    if (h >= 1 && h <= NH - 2) {
        unsigned char dm = g_diff[hw0];
        unsigned char dp = g_diff[hw0 + 1];
        if (w0 >= 1) bm0 = (float)(g_diff[hw0 - 1] | dm | dp);
        if (w0 + 1 <= NW - 2) bm1 = (float)(dm | dp | g_diff[hw0 + 2]);
    }

    const float2* p = (const float2*)in + tidg;          // class-stream base
    const int2* tp = (const int2*)tgt + tidg;
    const float* inb = in + hw0;                         // gather base

    float denom[NC];
#pragma unroll
    for (int c = 0; c < NC; c++) denom[c] = 0.0f;
    float a_focal = 0.0f, a_nll = 0.0f, a_slp = 0.0f, a_bnll = 0.0f;

#pragma unroll 1
    for (int b = 0; b < NB; b++) {
        const int2 tt = __ldg(tp);
        const int t0 = tt.x, t1 = tt.y;

        // single sweep: load, sum raw logits, exponentiate; keep only exps
        float2 e[NC];
        float sA0 = 0.f, sB0 = 0.f, sA1 = 0.f, sB1 = 0.f;
        float zA0 = 0.f, zB0 = 0.f, zA1 = 0.f, zB1 = 0.f;
#pragma unroll
        for (int c = 0; c < NC; c++) {
            float2 v = __ldg(p + (size_t)c * (HW / 2));
            float ex = __expf(v.x);
            float ey = __expf(v.y);
            if (c & 1) { sB0 += v.x; sB1 += v.y; zB0 += ex; zB1 += ey; }
            else       { sA0 += v.x; sA1 += v.y; zA0 += ex; zA1 += ey; }
            e[c].x = ex; e[c].y = ey;
        }
        const float sumx = (sA0 + sB0) + (sA1 + sB1);
        const float Z0 = zA0 + zB0;
        const float Z1 = zA1 + zB1;

        // raw target logits: gather from just-loaded lines (L1 hits)
        const float xt0 = __ldg(inb + (size_t)t0 * HW);
        const float xt1 = __ldg(inb + (size_t)t1 * HW + 1);

        const float invZ0 = __fdividef(1.0f, Z0);
        const float invZ1 = __fdividef(1.0f, Z1);
        const float logZ0 = __logf(Z0);
        const float logZ1 = __logf(Z1);
        const float nll0 = logZ0 - xt0;
        const float nll1 = logZ1 - xt1;
        const float pt0 = __expf(xt0) * invZ0;
        const float pt1 = __expf(xt1) * invZ1;

#pragma unroll
        for (int c = 0; c < NC; c++) {
            denom[c] = fmaf(e[c].x, invZ0, fmaf(e[c].y, invZ1, denom[c]));
        }

        const float om0 = 1.0f - pt0, om1 = 1.0f - pt1;
        a_focal = fmaf(om0 * om0, nll0, fmaf(om1 * om1, nll1, a_focal));
        a_nll += nll0 + nll1;
        a_slp += sumx - (float)NC * (logZ0 + logZ1);
        a_bnll = fmaf(nll0, bm0, fmaf(nll1, bm1, a_bnll));

        atomicAdd(&s_int[wid][t0], pt0);
        atomicAdd(&s_int[wid][t1], pt1);

        p += NC * (HW / 2);
        tp += HW / 2;
        inb += (size_t)NC * HW;
    }

    // --- block reduction ---
#pragma unroll
    for (int c = 0; c < NC; c++) {
        float v = warp_sum(denom[c]);
        if (lane == 0) atomicAdd(&s_blk[c], v);
    }
    {
        float v = warp_sum(a_focal);
        if (lane == 0) atomicAdd(&s_blk[38], v);
        v = warp_sum(a_nll);
        if (lane == 0) atomicAdd(&s_blk[39], v);
        v = warp_sum(a_slp);
        if (lane == 0) atomicAdd(&s_blk[40], v);
        v = warp_sum(a_bnll);
        if (lane == 0) atomicAdd(&s_blk[41], v);
    }
    __syncthreads();

    if (threadIdx.x < NC) {
        float vi = 0.0f;
#pragma unroll
        for (int wsel = 0; wsel < 8; wsel++) vi += s_int[wsel][threadIdx.x];
        atomicAdd(&g_acc[NC + threadIdx.x], vi);
    }
    if (threadIdx.x < NACC && (threadIdx.x < NC || threadIdx.x >= 38)) {
        atomicAdd(&g_acc[threadIdx.x], s_blk[threadIdx.x]);
    }

    // --- ticketed finalize + state cleanup (graph-replay safe) ---
    __threadfence();
    __syncthreads();
    if (threadIdx.x == 0)
        s_last = (atomicAdd(&g_ticket, 1u) == MAIN_BLOCKS - 1);
    __syncthreads();

    if (s_last && threadIdx.x < 32) {
        const float Ninv = 1.0f / (float)NPIX;
        float ps = (lane < NC) ? g_acc[lane] : 0.0f;
        float it = (lane < NC) ? g_acc[NC + lane] : 0.0f;
        float cn = (lane < NC) ? (float)g_cnt[lane] : 0.0f;
        float d = 0.0f;
        if (lane < NC) d = 1.0f - (2.0f * it + 1e-5f) / (ps + cn + 1e-5f);
        d = warp_sum(d);
        if (lane == 0) {
            float dice = d / (float)NC;
            float focal = g_acc[38] * Ninv;
            float nll_sum = g_acc[39];
            float slp_sum = g_acc[40];
            float ce = (0.9f * nll_sum - 0.1f * slp_sum / (float)NC) * Ninv;
            float boundary = (nll_sum + 0.5f * g_acc[41]) * Ninv;
            out[0] = focal;
            out[1] = dice;
            out[2] = ce;
            out[3] = boundary;
            out[4] = focal + dice + ce + boundary;
        }
        if (lane < NACC) g_acc[lane] = 0.0f;
        if (lane + 32 < NACC) g_acc[lane + 32] = 0.0f;
        if (lane < NC) g_cnt[lane] = 0;
        if (lane == 0) g_ticket = 0u;
    }
}

// ---------------------------------------------------------------------------
extern "C" void kernel_launch(void* const* d_in, const int* in_sizes, int n_in,
                              void* d_out, int out_size) {
    const float* inputs = (const float*)d_in[0];
    const int* targets = (const int*)d_in[1];
    float* out = (float*)d_out;

    diff_kernel<<<DG, DB>>>(targets);
    main_kernel<<<MAIN_BLOCKS, 256>>>(inputs, targets, out);
}